// round 16
// baseline (speedup 1.0000x reference)
#include <cuda_runtime.h>
#include <cuda_bf16.h>
#include <float.h>
#include <cstdint>

#define BB 8
#define NN 4096
#define CC 64
#define OO 64
#define KK 20
#define NEG_SLOPE 0.2f
#define EPS 1e-5f
#define DBLK 1024

typedef unsigned long long ull;

// ---------------- smem map for k_knn_wmma (128 threads, 128 queries, 128-cand tiles) ----
// OFF_A: A tile during init (128 x 272B), then reused as D scratch
//        (4 warps x 32 rows x 36 words = 18432B used)        -> 34816
// OFF_B: single B buffer (128 x 272B)                        -> 34816
// SSQ: 128 x 4B                                              -> 512
#define OFF_A   0
#define OFF_B   34816
#define OFF_SSQ 69632
#define DYN_BYTES 70144

__device__ __forceinline__ uint32_t smem_u32(const void* p) {
    uint32_t a;
    asm("{ .reg .u64 t; cvta.to.shared.u64 t, %1; cvt.u32.u64 %0, t; }" : "=r"(a) : "l"(p));
    return a;
}
__device__ __forceinline__ void ldsm4(uint32_t* r, uint32_t addr) {
    asm volatile("ldmatrix.sync.aligned.m8n8.x4.shared.b16 {%0,%1,%2,%3}, [%4];"
        : "=r"(r[0]), "=r"(r[1]), "=r"(r[2]), "=r"(r[3]) : "r"(addr));
}
__device__ __forceinline__ void mma_bf16(float* c, const uint32_t* a, const uint32_t* b) {
    asm volatile(
        "mma.sync.aligned.m16n8k16.row.col.f32.bf16.bf16.f32 "
        "{%0,%1,%2,%3}, {%4,%5,%6,%7}, {%8,%9}, {%0,%1,%2,%3};"
        : "+f"(c[0]), "+f"(c[1]), "+f"(c[2]), "+f"(c[3])
        : "r"(a[0]), "r"(a[1]), "r"(a[2]), "r"(a[3]), "r"(b[0]), "r"(b[1]));
}
#define CP_ASYNC16(sa, gp) \
    asm volatile("cp.async.cg.shared.global [%0], [%1], 16;" :: "r"(sa), "l"(gp))
#define CP_ASYNC4(sa, gp) \
    asm volatile("cp.async.ca.shared.global [%0], [%1], 4;" :: "r"(sa), "l"(gp))
#define CP_COMMIT() asm volatile("cp.async.commit_group;" ::: "memory")
#define CP_WAIT0()  asm volatile("cp.async.wait_group 0;" ::: "memory")

// ---------------- scratch ----------------
__device__ __align__(16) float g_xT[BB * NN * CC];
__device__ __align__(16) __nv_bfloat16 g_xs[BB * NN * 128];  // [hi(64)|lo(64)] per point
__device__ float g_sq[BB * NN];
__device__ __align__(16) float g_p[BB * NN * OO];
__device__ __align__(16) float g_q[BB * NN * OO];
__device__ int   g_idx[BB * NN * KK];
__device__ __align__(16) float g_ymax[BB * NN * OO];
__device__ __align__(16) float g_ymin[BB * NN * OO];
__device__ float g_part[DBLK * 2 * OO];
__device__ float g_stats[2 * OO];

// ---------------- A1: transpose (B,C,N) -> (B,N,C) + bf16 hi/lo split (fused) ----------
__global__ void k_transpose(const float* __restrict__ in) {
    __shared__ float t[32][33];
    int b = blockIdx.z, c0 = blockIdx.y * 32, n0 = blockIdx.x * 32;
    int tx = threadIdx.x, ty = threadIdx.y;
#pragma unroll
    for (int j = 0; j < 4; j++)
        t[ty + 8 * j][tx] = in[((size_t)b * CC + (c0 + ty + 8 * j)) * NN + n0 + tx];
    __syncthreads();
#pragma unroll
    for (int j = 0; j < 4; j++) {
        float v = t[tx][ty + 8 * j];
        size_t point = (size_t)b * NN + (n0 + ty + 8 * j);
        int c = c0 + tx;
        g_xT[point * CC + c] = v;
        __nv_bfloat16 h = __float2bfloat16_rn(v);
        __nv_bfloat16 l = __float2bfloat16_rn(v - __bfloat162float(h));
        g_xs[point * 128 + c] = h;
        g_xs[point * 128 + 64 + c] = l;
    }
}

// ---------------- A2: squared norms + p,q projections ----------------
__global__ void k_pq(const float* __restrict__ W) {
    __shared__ float sWp[OO][CC];
    __shared__ float sWd[OO][CC];
    int tid = threadIdx.x;
    for (int i = tid; i < OO * CC; i += 128) {
        int o = i >> 6, c = i & 63;
        float wp = W[o * 2 * CC + c];
        sWp[o][c] = wp;
        sWd[o][c] = W[o * 2 * CC + CC + c] - wp;
    }
    __syncthreads();
    int point = blockIdx.x * 128 + tid;
    const float4* xr4 = reinterpret_cast<const float4*>(g_xT + (size_t)point * CC);
    float xr[CC];
    float sq = 0.f;
#pragma unroll
    for (int i = 0; i < 16; i++) {
        float4 v = xr4[i];
        xr[4 * i] = v.x; xr[4 * i + 1] = v.y; xr[4 * i + 2] = v.z; xr[4 * i + 3] = v.w;
        sq = fmaf(v.x, v.x, sq); sq = fmaf(v.y, v.y, sq);
        sq = fmaf(v.z, v.z, sq); sq = fmaf(v.w, v.w, sq);
    }
    g_sq[point] = sq;
    float* pp = g_p + (size_t)point * OO;
    float* qq = g_q + (size_t)point * OO;
#pragma unroll 1
    for (int o = 0; o < OO; o++) {
        const float4* wp4 = reinterpret_cast<const float4*>(&sWp[o][0]);
        const float4* wd4 = reinterpret_cast<const float4*>(&sWd[o][0]);
        float ap = 0.f, aq = 0.f;
#pragma unroll
        for (int i = 0; i < 16; i++) {
            float4 wp = wp4[i], wd = wd4[i];
            ap = fmaf(xr[4 * i], wp.x, ap); ap = fmaf(xr[4 * i + 1], wp.y, ap);
            ap = fmaf(xr[4 * i + 2], wp.z, ap); ap = fmaf(xr[4 * i + 3], wp.w, ap);
            aq = fmaf(xr[4 * i], wd.x, aq); aq = fmaf(xr[4 * i + 1], wd.y, aq);
            aq = fmaf(xr[4 * i + 2], wd.z, aq); aq = fmaf(xr[4 * i + 3], wd.w, aq);
        }
        pp[o] = ap;
        qq[o] = aq;
    }
}

// ===================== B: HMMA distance GEMM + sorted-register top-20 =====================
// 128-thread CTA, 128 queries, 128-cand B tiles; 3 CTAs/SM (70KB smem, regs<=170).
// A fragments loaded ONCE into registers; A's smem region then becomes the D scratch.
// Each warp: 32 rows x 128 cols per tile via FOUR 32-col quarters (cacc = 32 regs).
// B fragments deduped: B-hi feeds hi*hi + lo*hi (8 MMA/load); B-lo feeds hi*lo (4/load).
// acc = hi·hi + lo·hi + hi·lo ≈ fp32 dot; acc init -||x_m||^2/2 => D' = dot - sq/2.
// Each lane owns one complete query row (sorted-register top-20, static indices).
__global__ void __launch_bounds__(128, 3) k_knn_wmma() {
    extern __shared__ __align__(16) char sm[];
    int tid = threadIdx.x;
    int w = tid >> 5, lane = tid & 31;
    int b = blockIdx.y, r0 = blockIdx.x * 128, bbase = b * NN;
    const char* xsrc = (const char*)g_xs;
    uint32_t sbase = smem_u32(sm);

    // ---- A tile into OFF_A: 128 rows x 256B data, 272B stride ----
#pragma unroll
    for (int i = 0; i < 16; i++) {
        int u = tid + 128 * i;
        int row = u >> 4, c = u & 15;
        uint4 v = *reinterpret_cast<const uint4*>(xsrc + (size_t)(bbase + r0 + row) * 256 + c * 16);
        *reinterpret_cast<uint4*>(sm + OFF_A + row * 272 + c * 16) = v;
    }

    // ---- B tile 0 + ssq via cp.async ----
#pragma unroll
    for (int i = 0; i < 16; i++) {
        int u = tid + 128 * i;
        int row = u >> 4, c = u & 15;
        CP_ASYNC16(sbase + OFF_B + row * 272 + c * 16,
                   xsrc + (size_t)(bbase + row) * 256 + c * 16);
    }
    CP_ASYNC4(sbase + OFF_SSQ + tid * 4, &g_sq[bbase + tid]);
    CP_COMMIT();

    // ---- sorted top-20 state (registers, static indices only) ----
    float sv[20]; int si[20];
#pragma unroll
    for (int j = 0; j < 20; j++) { sv[j] = -FLT_MAX; si[j] = 0; }

    // A ldsm base per row-subblock i (i=0,1): rows w*32 + i*16 (OFF_A, pre-reuse)
    uint32_t aab0 = sbase + OFF_A + (w * 32 + (lane & 15)) * 272 + (lane >> 4) * 16;
    uint32_t aab1 = aab0 + 16 * 272;
    // B ldsm lane offset within a 32-col quarter: t2 (0,1) adds t2*16 rows (4352B)
    uint32_t blane = ((lane & 7) + ((lane >> 4) << 3)) * 272 + (((lane >> 3) & 1) * 16);
    // D scratch lives in the (dead after frag load) OFF_A region
    float* Dwarp = reinterpret_cast<float*>(sm + OFF_A + w * 4608);   // 32 x 36 words
    float* Drow = Dwarp + lane * 36;

    int rl = lane >> 2, cl = (lane & 3) * 2;

    // ---- A fragments resident in registers (tile-invariant) ----
    __syncthreads();   // A smem stores visible before ldsm
    uint32_t afh[4][2][4];   // hi chunk s, row-subblock i
    uint32_t afl[4][2][4];   // lo chunk s, row-subblock i
#pragma unroll
    for (int s = 0; s < 4; s++) {
        ldsm4(afh[s][0], aab0 + s * 32);
        ldsm4(afh[s][1], aab1 + s * 32);
        ldsm4(afl[s][0], aab0 + 128 + s * 32);
        ldsm4(afl[s][1], aab1 + 128 + s * 32);
    }
    // NOTE: the loop's first __syncthreads (below) separates these ldsm reads from
    // the first D-scratch stores into the same region.

#define MMA_QTR(cacc, bq, sp)                                                   \
    {                                                                           \
        _Pragma("unroll")                                                       \
        for (int t2 = 0; t2 < 2; t2++)                                          \
            _Pragma("unroll")                                                   \
            for (int h = 0; h < 2; h++) {                                       \
                float2 svv = (sp)[t2 * 8 + h * 4 + (lane & 3)];                 \
                float v0 = -0.5f * svv.x, v1 = -0.5f * svv.y;                   \
                _Pragma("unroll")                                               \
                for (int i = 0; i < 2; i++) {                                   \
                    cacc[i][t2][h][0] = v0; cacc[i][t2][h][1] = v1;             \
                    cacc[i][t2][h][2] = v0; cacc[i][t2][h][3] = v1;             \
                }                                                               \
            }                                                                   \
        /* B-hi chunks: feed hi*hi and lo*hi (8 MMAs per fragment load) */      \
        _Pragma("unroll")                                                       \
        for (int s = 0; s < 4; s++)                                             \
            _Pragma("unroll")                                                   \
            for (int t2 = 0; t2 < 2; t2++) {                                    \
                uint32_t bfr[4];                                                \
                ldsm4(bfr, (bq) + t2 * 4352 + s * 32);                          \
                mma_bf16(cacc[0][t2][0], afh[s][0], bfr);                       \
                mma_bf16(cacc[0][t2][1], afh[s][0], bfr + 2);                   \
                mma_bf16(cacc[1][t2][0], afh[s][1], bfr);                       \
                mma_bf16(cacc[1][t2][1], afh[s][1], bfr + 2);                   \
                mma_bf16(cacc[0][t2][0], afl[s][0], bfr);                       \
                mma_bf16(cacc[0][t2][1], afl[s][0], bfr + 2);                   \
                mma_bf16(cacc[1][t2][0], afl[s][1], bfr);                       \
                mma_bf16(cacc[1][t2][1], afl[s][1], bfr + 2);                   \
            }                                                                   \
        /* B-lo chunks: feed hi*lo (4 MMAs per fragment load) */                \
        _Pragma("unroll")                                                       \
        for (int s = 0; s < 4; s++)                                             \
            _Pragma("unroll")                                                   \
            for (int t2 = 0; t2 < 2; t2++) {                                    \
                uint32_t bfr[4];                                                \
                ldsm4(bfr, (bq) + t2 * 4352 + 128 + s * 32);                    \
                mma_bf16(cacc[0][t2][0], afh[s][0], bfr);                       \
                mma_bf16(cacc[0][t2][1], afh[s][0], bfr + 2);                   \
                mma_bf16(cacc[1][t2][0], afh[s][1], bfr);                       \
                mma_bf16(cacc[1][t2][1], afh[s][1], bfr + 2);                   \
            }                                                                   \
    }

#define STORE_QTR(cacc)                                                         \
    {                                                                           \
        _Pragma("unroll")                                                       \
        for (int i = 0; i < 2; i++)                                             \
            _Pragma("unroll")                                                   \
            for (int t2 = 0; t2 < 2; t2++)                                      \
                _Pragma("unroll")                                               \
                for (int h = 0; h < 2; h++) {                                   \
                    int col = t2 * 16 + h * 8 + cl;                             \
                    float* base = Dwarp + (i * 16 + rl) * 36 + col;             \
                    *reinterpret_cast<float2*>(base) =                          \
                        make_float2(cacc[i][t2][h][0], cacc[i][t2][h][1]);      \
                    *reinterpret_cast<float2*>(base + 8 * 36) =                 \
                        make_float2(cacc[i][t2][h][2], cacc[i][t2][h][3]);      \
                }                                                               \
    }

#define SCAN_QTR(q)                                                             \
    {                                                                           \
        unsigned pend = 0;                                                      \
        _Pragma("unroll")                                                       \
        for (int i = 0; i < 8; i++) {                                           \
            float4 d = *reinterpret_cast<const float4*>(Drow + 4 * i);          \
            if (d.x > sv[19]) pend |= (1u << (4 * i));                          \
            if (d.y > sv[19]) pend |= (1u << (4 * i + 1));                      \
            if (d.z > sv[19]) pend |= (1u << (4 * i + 2));                      \
            if (d.w > sv[19]) pend |= (1u << (4 * i + 3));                      \
        }                                                                       \
        while (pend) {                                                          \
            int slot = __ffs(pend) - 1;                                         \
            pend &= pend - 1;                                                   \
            float v = Drow[slot];                                               \
            if (v > sv[19]) {                                                   \
                int ix = mt + (q) * 32 + slot;                                  \
                _Pragma("unroll")                                               \
                for (int j = 19; j > 0; j--) {                                  \
                    bool up = v > sv[j - 1];                                    \
                    bool mid = v > sv[j];                                       \
                    sv[j] = up ? sv[j - 1] : (mid ? v : sv[j]);                 \
                    si[j] = up ? si[j - 1] : (mid ? ix : si[j]);                \
                }                                                               \
                if (v > sv[0]) { sv[0] = v; si[0] = ix; }                       \
            }                                                                   \
        }                                                                       \
    }

#pragma unroll 1
    for (int t = 0; t < 32; t++) {
        int mt = t * 128;
        uint32_t bB = sbase + OFF_B + blane;
        const float2* ssq2 = reinterpret_cast<const float2*>(sm + OFF_SSQ);

        CP_WAIT0();          // B[t] + ssq landed (issuing-thread view)
        __syncthreads();     // cross-thread visibility (also guards D-region reuse)

        float cacc[2][2][2][4];

        // quarters 0..2: MMA + store + scan
#pragma unroll 1
        for (int q = 0; q < 3; q++) {
            MMA_QTR(cacc, bB + q * 8704, ssq2 + q * 16)
            STORE_QTR(cacc)
            __syncwarp();
            SCAN_QTR(q)
            __syncwarp();
        }

        // quarter 3: MMA (last B read), then barrier + prefetch, then store + scan
        MMA_QTR(cacc, bB + 3 * 8704, ssq2 + 48)
        __syncthreads();     // all warps done reading B before overwrite
        if (t < 31) {
            int nmt = mt + 128;
#pragma unroll
            for (int i = 0; i < 16; i++) {
                int u = tid + 128 * i;
                int row = u >> 4, c = u & 15;
                CP_ASYNC16(sbase + OFF_B + row * 272 + c * 16,
                           xsrc + (size_t)(bbase + nmt + row) * 256 + c * 16);
            }
            CP_ASYNC4(sbase + OFF_SSQ + tid * 4, &g_sq[bbase + nmt + tid]);
            CP_COMMIT();
        }
        STORE_QTR(cacc)
        __syncwarp();
        SCAN_QTR(3)
    }

    // ---- output: each lane owns one complete row ----
    int row_pt = bbase + r0 + w * 32 + lane;
    int* op = g_idx + (size_t)row_pt * KK;
#pragma unroll
    for (int j = 0; j < KK; j++) op[j] = si[j];
}

// ---------------- D: gather p[idx]+q, max/min over k, BN partial sums ----------------
__global__ void k_gather() {
    int tid = threadIdx.x;  // 256
    int g = tid >> 6, o = tid & 63;
    float psum = 0.f, psq = 0.f;
#pragma unroll 1
    for (int i = 0; i < 8; i++) {
        int point = blockIdx.x * 32 + i * 4 + g;
        int b = point >> 12;
        const int* ix = g_idx + (size_t)point * KK;
        float qv = g_q[(size_t)point * OO + o];
        const float* pb = g_p + (((size_t)b) << 12) * OO;
        float mx = -FLT_MAX, mn = FLT_MAX;
#pragma unroll
        for (int k = 0; k < KK; k++) {
            int j = ix[k];
            float y = pb[(size_t)j * OO + o] + qv;
            mx = fmaxf(mx, y);
            mn = fminf(mn, y);
            psum += y;
            psq = fmaf(y, y, psq);
        }
        g_ymax[(size_t)point * OO + o] = mx;
        g_ymin[(size_t)point * OO + o] = mn;
    }
    __shared__ float ss[256], s2[256];
    ss[tid] = psum; s2[tid] = psq;
    __syncthreads();
    if (tid < 64) {
        float a = ss[tid] + ss[tid + 64] + ss[tid + 128] + ss[tid + 192];
        float c = s2[tid] + s2[tid + 64] + s2[tid + 128] + s2[tid + 192];
        g_part[(size_t)blockIdx.x * 128 + tid] = a;
        g_part[(size_t)blockIdx.x * 128 + 64 + tid] = c;
    }
}

__global__ void k_reduce() {
    int i = blockIdx.x;
    int t = threadIdx.x;
    float s = 0.f;
    for (int blk = t; blk < DBLK; blk += 256) s += g_part[(size_t)blk * 128 + i];
    __shared__ float smr[256];
    smr[t] = s;
    __syncthreads();
    for (int wd = 128; wd > 0; wd >>= 1) {
        if (t < wd) smr[t] += smr[t + wd];
        __syncthreads();
    }
    if (t == 0) g_stats[i] = smr[0];
}

__global__ void k_out(const float* __restrict__ gamma, const float* __restrict__ beta,
                      float* __restrict__ out) {
    __shared__ float smT[OO][33];
    int b = blockIdx.y, n0 = blockIdx.x * 32;
    int tid = threadIdx.x;
    const float CNTf = (float)(BB * NN * KK);
#pragma unroll 1
    for (int i = tid; i < 32 * OO; i += 256) {
        int n = i >> 6, o = i & 63;
        float s = g_stats[o], s2v = g_stats[64 + o];
        float mean = s / CNTf;
        float var = s2v / CNTf - mean * mean;
        float rstd = rsqrtf(var + EPS);
        float gm = gamma[o];
        size_t yi = ((size_t)b * NN + n0 + n) * OO + o;
        float v = (gm >= 0.f) ? g_ymax[yi] : g_ymin[yi];
        float z = gm * (v - mean) * rstd + beta[o];
        z = (z >= 0.f) ? z : NEG_SLOPE * z;
        smT[o][n] = z;
    }
    __syncthreads();
#pragma unroll 1
    for (int i = tid; i < OO * 32; i += 256) {
        int o = i >> 5, n = i & 31;
        out[((size_t)b * OO + o) * NN + n0 + n] = smT[o][n];
    }
}

extern "C" void kernel_launch(void* const* d_in, const int* in_sizes, int n_in,
                              void* d_out, int out_size) {
    const float* inp = (const float*)d_in[0];
    const float* W = (const float*)d_in[1];
    const float* gamma = (const float*)d_in[2];
    const float* beta = (const float*)d_in[3];
    float* out = (float*)d_out;

    cudaFuncSetAttribute(k_knn_wmma, cudaFuncAttributeMaxDynamicSharedMemorySize, DYN_BYTES);

    k_transpose<<<dim3(NN / 32, CC / 32, BB), dim3(32, 8)>>>(inp);
    k_pq<<<BB * NN / 128, 128>>>(W);
    k_knn_wmma<<<dim3(NN / 128, BB), 128, DYN_BYTES>>>();
    k_gather<<<DBLK, 256>>>();
    k_reduce<<<2 * OO, 256>>>();
    k_out<<<dim3(NN / 32, BB), 256>>>(gamma, beta, out);
}

// round 17
// speedup vs baseline: 1.1823x; 1.1823x over previous
#include <cuda_runtime.h>
#include <cuda_bf16.h>
#include <float.h>
#include <cstdint>

#define BB 8
#define NN 4096
#define CC 64
#define OO 64
#define KK 20
#define NEG_SLOPE 0.2f
#define EPS 1e-5f
#define DBLK 1024

typedef unsigned long long ull;

// ---------------- smem map for k_knn_wmma (128 threads, 128 queries, 128-cand tiles) ----
// BUF0 (A tile at start, then B ping buffer): 128 x 272B -> 34816
// BUF1 (B pong buffer):                       128 x 272B -> 34816
// D: 4 warps x 32 rows x 68 words             -> 34816
// SSQ: 2 x 128 x 4B                           -> 1024
#define OFF_A   0
#define OFF_B   34816
#define OFF_D   69632
#define OFF_SSQ 104448
#define DYN_BYTES 105472

// ---------------- smem map for k_prep ----------------
// sWp 16KB | sWd 16KB | stage 32KB
#define PREP_WP 0
#define PREP_WD 16384
#define PREP_ST 32768
#define PREP_BYTES 65536

__device__ __forceinline__ uint32_t smem_u32(const void* p) {
    uint32_t a;
    asm("{ .reg .u64 t; cvta.to.shared.u64 t, %1; cvt.u32.u64 %0, t; }" : "=r"(a) : "l"(p));
    return a;
}
__device__ __forceinline__ void ldsm4(uint32_t* r, uint32_t addr) {
    asm volatile("ldmatrix.sync.aligned.m8n8.x4.shared.b16 {%0,%1,%2,%3}, [%4];"
        : "=r"(r[0]), "=r"(r[1]), "=r"(r[2]), "=r"(r[3]) : "r"(addr));
}
__device__ __forceinline__ void mma_bf16(float* c, const uint32_t* a, const uint32_t* b) {
    asm volatile(
        "mma.sync.aligned.m16n8k16.row.col.f32.bf16.bf16.f32 "
        "{%0,%1,%2,%3}, {%4,%5,%6,%7}, {%8,%9}, {%0,%1,%2,%3};"
        : "+f"(c[0]), "+f"(c[1]), "+f"(c[2]), "+f"(c[3])
        : "r"(a[0]), "r"(a[1]), "r"(a[2]), "r"(a[3]), "r"(b[0]), "r"(b[1]));
}
#define CP_ASYNC16(sa, gp) \
    asm volatile("cp.async.cg.shared.global [%0], [%1], 16;" :: "r"(sa), "l"(gp))
#define CP_ASYNC4(sa, gp) \
    asm volatile("cp.async.ca.shared.global [%0], [%1], 4;" :: "r"(sa), "l"(gp))
#define CP_COMMIT() asm volatile("cp.async.commit_group;" ::: "memory")
#define CP_WAIT0()  asm volatile("cp.async.wait_group 0;" ::: "memory")

// ---------------- scratch ----------------
__device__ __align__(16) __nv_bfloat16 g_xs[BB * NN * 128];  // [hi(64)|lo(64)] per point
__device__ float g_sq[BB * NN];
__device__ __align__(16) float g_p[BB * NN * OO];
__device__ __align__(16) float g_q[BB * NN * OO];
__device__ int   g_idx[BB * NN * KK];
__device__ __align__(16) float g_ymax[BB * NN * OO];
__device__ __align__(16) float g_ymin[BB * NN * OO];
__device__ float g_part[DBLK * 2 * OO];
__device__ float g_stats[2 * OO];

// ---------------- A: fused prep — reads (B,C,N) input directly (coalesced over n).
// Produces: g_xs (bf16 hi/lo, staged via smem for coalesced writes), g_sq, g_p, g_q.
__global__ void k_prep(const float* __restrict__ in, const float* __restrict__ W) {
    extern __shared__ __align__(16) char psm[];
    float* sWp = reinterpret_cast<float*>(psm + PREP_WP);   // [64][64]
    float* sWd = reinterpret_cast<float*>(psm + PREP_WD);   // [64][64]
    char* stage = psm + PREP_ST;                             // 128 x 256B

    int tid = threadIdx.x;  // 128
    for (int i = tid; i < OO * CC; i += 128) {
        int o = i >> 6, c = i & 63;
        float wp = W[o * 2 * CC + c];
        sWp[o * CC + c] = wp;
        sWd[o * CC + c] = W[o * 2 * CC + CC + c] - wp;
    }

    int point = blockIdx.x * 128 + tid;
    int b = point >> 12, n = point & (NN - 1);

    // coalesced load of x row: lane-consecutive n for each c
    float xr[CC];
    float sq = 0.f;
#pragma unroll
    for (int c = 0; c < CC; c++) {
        float v = in[((size_t)b * CC + c) * NN + n];
        xr[c] = v;
        sq = fmaf(v, v, sq);
    }
    g_sq[point] = sq;

    // bf16 hi/lo split into staging (tid-local 256B row)
    char* myst = stage + tid * 256;
#pragma unroll
    for (int i = 0; i < 16; i++) {
        float f0 = xr[4 * i], f1 = xr[4 * i + 1], f2 = xr[4 * i + 2], f3 = xr[4 * i + 3];
        __nv_bfloat16 h0 = __float2bfloat16_rn(f0), h1 = __float2bfloat16_rn(f1);
        __nv_bfloat16 h2 = __float2bfloat16_rn(f2), h3 = __float2bfloat16_rn(f3);
        __nv_bfloat162 hp0(h0, h1), hp1(h2, h3);
        __nv_bfloat162 lp0(__float2bfloat16_rn(f0 - __bfloat162float(h0)),
                           __float2bfloat16_rn(f1 - __bfloat162float(h1)));
        __nv_bfloat162 lp1(__float2bfloat16_rn(f2 - __bfloat162float(h2)),
                           __float2bfloat16_rn(f3 - __bfloat162float(h3)));
        *reinterpret_cast<__nv_bfloat162*>(myst + i * 8) = hp0;
        *reinterpret_cast<__nv_bfloat162*>(myst + i * 8 + 4) = hp1;
        *reinterpret_cast<__nv_bfloat162*>(myst + 128 + i * 8) = lp0;
        *reinterpret_cast<__nv_bfloat162*>(myst + 128 + i * 8 + 4) = lp1;
    }
    __syncthreads();

    // coalesced copy staging -> g_xs
    {
        const uint4* src = reinterpret_cast<const uint4*>(stage);
        uint4* dst = reinterpret_cast<uint4*>((char*)g_xs + (size_t)blockIdx.x * 128 * 256);
#pragma unroll
        for (int i = 0; i < 16; i++) {
            int idx = tid + 128 * i;
            dst[idx] = src[idx];
        }
    }

    // p, q projections
    float* pp = g_p + (size_t)point * OO;
    float* qq = g_q + (size_t)point * OO;
#pragma unroll 1
    for (int o = 0; o < OO; o++) {
        const float4* wp4 = reinterpret_cast<const float4*>(sWp + o * CC);
        const float4* wd4 = reinterpret_cast<const float4*>(sWd + o * CC);
        float ap = 0.f, aq = 0.f;
#pragma unroll
        for (int i = 0; i < 16; i++) {
            float4 wp = wp4[i], wd = wd4[i];
            ap = fmaf(xr[4 * i], wp.x, ap); ap = fmaf(xr[4 * i + 1], wp.y, ap);
            ap = fmaf(xr[4 * i + 2], wp.z, ap); ap = fmaf(xr[4 * i + 3], wp.w, ap);
            aq = fmaf(xr[4 * i], wd.x, aq); aq = fmaf(xr[4 * i + 1], wd.y, aq);
            aq = fmaf(xr[4 * i + 2], wd.z, aq); aq = fmaf(xr[4 * i + 3], wd.w, aq);
        }
        pp[o] = ap;
        qq[o] = aq;
    }
}

// ===================== B: HMMA distance GEMM + sorted-register top-20 =====================
// (r15 champion structure, unchanged) 128-thread CTA, 128 queries, 128-cand B tiles;
// 2 CTAs/SM. Each warp owns 32 rows x FULL 128-col tile via two 64-col passes; each lane
// owns one complete query row. A fragments loaded ONCE into registers; A's smem region is
// then reused as the second B buffer (ping-pong) -> ONE barrier per tile, full-tile
// prefetch window. B fragments deduped: B-hi feeds hi*hi + lo*hi; B-lo feeds hi*lo.
// acc = hi·hi + lo·hi + hi·lo ≈ fp32 dot; acc init -||x_m||^2/2 => D' = dot - sq/2.
__global__ void __launch_bounds__(128, 2) k_knn_wmma() {
    extern __shared__ __align__(16) char sm[];
    int tid = threadIdx.x;
    int w = tid >> 5, lane = tid & 31;
    int b = blockIdx.y, r0 = blockIdx.x * 128, bbase = b * NN;
    const char* xsrc = (const char*)g_xs;
    uint32_t sbase = smem_u32(sm);

    // ---- A tile into BUF0 (OFF_A): 128 rows x 256B data, 272B stride ----
#pragma unroll
    for (int i = 0; i < 16; i++) {
        int u = tid + 128 * i;
        int row = u >> 4, c = u & 15;
        uint4 v = *reinterpret_cast<const uint4*>(xsrc + (size_t)(bbase + r0 + row) * 256 + c * 16);
        *reinterpret_cast<uint4*>(sm + OFF_A + row * 272 + c * 16) = v;
    }

    // ---- B tile 0 into BUF_B (OFF_B) + ssq slot 0 via cp.async ----
#pragma unroll
    for (int i = 0; i < 16; i++) {
        int u = tid + 128 * i;
        int row = u >> 4, c = u & 15;
        CP_ASYNC16(sbase + OFF_B + row * 272 + c * 16,
                   xsrc + (size_t)(bbase + row) * 256 + c * 16);
    }
    CP_ASYNC4(sbase + OFF_SSQ + tid * 4, &g_sq[bbase + tid]);
    CP_COMMIT();

    // ---- sorted top-20 state (registers, static indices only) ----
    float sv[20]; int si[20];
#pragma unroll
    for (int j = 0; j < 20; j++) { sv[j] = -FLT_MAX; si[j] = 0; }

    // A ldsm base per row-subblock i (i=0,1): rows w*32 + i*16 (in OFF_A before reuse)
    uint32_t aab0 = sbase + OFF_A + (w * 32 + (lane & 15)) * 272 + (lane >> 4) * 16;
    uint32_t aab1 = aab0 + 16 * 272;
    // B ldsm lane offset within a 64-col half: t2 adds t2*16 rows (4352B)
    uint32_t blane = ((lane & 7) + ((lane >> 4) << 3)) * 272 + (((lane >> 3) & 1) * 16);
    float* Dwarp = reinterpret_cast<float*>(sm + OFF_D + w * 8704);   // 32 x 68 words
    float* Drow = Dwarp + lane * 68;

    int rl = lane >> 2, cl = (lane & 3) * 2;

    // ---- A fragments resident in registers (tile-invariant); then OFF_A becomes B pong ----
    __syncthreads();   // A smem stores visible before ldsm
    uint32_t afh[4][2][4];   // hi chunk s, row-subblock i
    uint32_t afl[4][2][4];   // lo chunk s, row-subblock i
#pragma unroll
    for (int s = 0; s < 4; s++) {
        ldsm4(afh[s][0], aab0 + s * 32);
        ldsm4(afh[s][1], aab1 + s * 32);
        ldsm4(afl[s][0], aab0 + 128 + s * 32);
        ldsm4(afl[s][1], aab1 + 128 + s * 32);
    }

#define MMA_PASS(cacc, babh, sp)                                                \
    {                                                                           \
        _Pragma("unroll")                                                       \
        for (int t2 = 0; t2 < 4; t2++)                                          \
            _Pragma("unroll")                                                   \
            for (int h = 0; h < 2; h++) {                                       \
                float2 svv = (sp)[t2 * 8 + h * 4 + (lane & 3)];                 \
                float v0 = -0.5f * svv.x, v1 = -0.5f * svv.y;                   \
                _Pragma("unroll")                                               \
                for (int i = 0; i < 2; i++) {                                   \
                    cacc[i][t2][h][0] = v0; cacc[i][t2][h][1] = v1;             \
                    cacc[i][t2][h][2] = v0; cacc[i][t2][h][3] = v1;             \
                }                                                               \
            }                                                                   \
        /* B-hi chunks: feed hi*hi and lo*hi (8 MMAs per fragment load) */      \
        _Pragma("unroll")                                                       \
        for (int s = 0; s < 4; s++)                                             \
            _Pragma("unroll")                                                   \
            for (int t2 = 0; t2 < 4; t2++) {                                    \
                uint32_t bfr[4];                                                \
                ldsm4(bfr, (babh) + t2 * 4352 + s * 32);                        \
                mma_bf16(cacc[0][t2][0], afh[s][0], bfr);                       \
                mma_bf16(cacc[0][t2][1], afh[s][0], bfr + 2);                   \
                mma_bf16(cacc[1][t2][0], afh[s][1], bfr);                       \
                mma_bf16(cacc[1][t2][1], afh[s][1], bfr + 2);                   \
                mma_bf16(cacc[0][t2][0], afl[s][0], bfr);                       \
                mma_bf16(cacc[0][t2][1], afl[s][0], bfr + 2);                   \
                mma_bf16(cacc[1][t2][0], afl[s][1], bfr);                       \
                mma_bf16(cacc[1][t2][1], afl[s][1], bfr + 2);                   \
            }                                                                   \
        /* B-lo chunks: feed hi*lo (4 MMAs per fragment load) */                \
        _Pragma("unroll")                                                       \
        for (int s = 0; s < 4; s++)                                             \
            _Pragma("unroll")                                                   \
            for (int t2 = 0; t2 < 4; t2++) {                                    \
                uint32_t bfr[4];                                                \
                ldsm4(bfr, (babh) + t2 * 4352 + 128 + s * 32);                  \
                mma_bf16(cacc[0][t2][0], afh[s][0], bfr);                       \
                mma_bf16(cacc[0][t2][1], afh[s][0], bfr + 2);                   \
                mma_bf16(cacc[1][t2][0], afh[s][1], bfr);                       \
                mma_bf16(cacc[1][t2][1], afh[s][1], bfr + 2);                   \
            }                                                                   \
    }

#define STORE_PASS(cacc)                                                        \
    {                                                                           \
        _Pragma("unroll")                                                       \
        for (int i = 0; i < 2; i++)                                             \
            _Pragma("unroll")                                                   \
            for (int t2 = 0; t2 < 4; t2++)                                      \
                _Pragma("unroll")                                               \
                for (int h = 0; h < 2; h++) {                                   \
                    int col = t2 * 16 + h * 8 + cl;                             \
                    float* base = Dwarp + (i * 16 + rl) * 68 + col;             \
                    *reinterpret_cast<float2*>(base) =                          \
                        make_float2(cacc[i][t2][h][0], cacc[i][t2][h][1]);      \
                    *reinterpret_cast<float2*>(base + 8 * 68) =                 \
                        make_float2(cacc[i][t2][h][2], cacc[i][t2][h][3]);      \
                }                                                               \
    }

#define SCAN_PASS(half)                                                         \
    {                                                                           \
        ull pend = 0;                                                           \
        _Pragma("unroll")                                                       \
        for (int i = 0; i < 16; i++) {                                          \
            float4 d = *reinterpret_cast<const float4*>(Drow + 4 * i);          \
            if (d.x > sv[19]) pend |= (1ull << (4 * i));                        \
            if (d.y > sv[19]) pend |= (1ull << (4 * i + 1));                    \
            if (d.z > sv[19]) pend |= (1ull << (4 * i + 2));                    \
            if (d.w > sv[19]) pend |= (1ull << (4 * i + 3));                    \
        }                                                                       \
        while (pend) {                                                          \
            int slot = __ffsll(pend) - 1;                                       \
            pend &= pend - 1;                                                   \
            float v = Drow[slot];                                               \
            if (v > sv[19]) {                                                   \
                int ix = mt + (half) * 64 + slot;                               \
                _Pragma("unroll")                                               \
                for (int j = 19; j > 0; j--) {                                  \
                    bool up = v > sv[j - 1];                                    \
                    bool mid = v > sv[j];                                       \
                    sv[j] = up ? sv[j - 1] : (mid ? v : sv[j]);                 \
                    si[j] = up ? si[j - 1] : (mid ? ix : si[j]);                \
                }                                                               \
                if (v > sv[0]) { sv[0] = v; si[0] = ix; }                       \
            }                                                                   \
        }                                                                       \
    }

#pragma unroll 1
    for (int t = 0; t < 32; t++) {
        int mt = t * 128;
        int buf = t & 1;
        // tile t reads bufs[buf]: buf0 = OFF_B, buf1 = OFF_A (dead A region)
        uint32_t bB = sbase + (buf ? OFF_A : OFF_B);
        const float2* ssq2 = reinterpret_cast<const float2*>(sm + OFF_SSQ + buf * 512);

        CP_WAIT0();          // B[t] + ssq[t] landed (issuing-thread view)
        __syncthreads();     // visibility + all warps done with the other buffer (t-1)

        // ---- prefetch B[t+1] into the other buffer (overlaps full tile) ----
        if (t < 31) {
            int nmt = mt + 128;
            uint32_t nB = sbase + (buf ? OFF_B : OFF_A);
#pragma unroll
            for (int i = 0; i < 16; i++) {
                int u = tid + 128 * i;
                int row = u >> 4, c = u & 15;
                CP_ASYNC16(nB + row * 272 + c * 16,
                           xsrc + (size_t)(bbase + nmt + row) * 256 + c * 16);
            }
            CP_ASYNC4(sbase + OFF_SSQ + (buf ^ 1) * 512 + tid * 4, &g_sq[bbase + nmt + tid]);
            CP_COMMIT();
        }

        float cacc[2][4][2][4];

        // ---- pass 0: cols 0-63 ----
        MMA_PASS(cacc, bB + blane, ssq2)
        STORE_PASS(cacc)
        __syncwarp();
        SCAN_PASS(0)
        __syncwarp();

        // ---- pass 1: cols 64-127 ----
        MMA_PASS(cacc, bB + blane + 4 * 4352, ssq2 + 32)
        STORE_PASS(cacc)
        __syncwarp();
        SCAN_PASS(1)
    }

    // ---- output: each lane owns one complete row ----
    int row_pt = bbase + r0 + w * 32 + lane;
    int* op = g_idx + (size_t)row_pt * KK;
#pragma unroll
    for (int j = 0; j < KK; j++) op[j] = si[j];
}

// ---------------- D: gather p[idx]+q, max/min over k, BN partial sums ----------------
__global__ void k_gather() {
    int tid = threadIdx.x;  // 256
    int g = tid >> 6, o = tid & 63;
    float psum = 0.f, psq = 0.f;
#pragma unroll 1
    for (int i = 0; i < 8; i++) {
        int point = blockIdx.x * 32 + i * 4 + g;
        int b = point >> 12;
        const int* ix = g_idx + (size_t)point * KK;
        float qv = g_q[(size_t)point * OO + o];
        const float* pb = g_p + (((size_t)b) << 12) * OO;
        float mx = -FLT_MAX, mn = FLT_MAX;
#pragma unroll
        for (int k = 0; k < KK; k++) {
            int j = ix[k];
            float y = pb[(size_t)j * OO + o] + qv;
            mx = fmaxf(mx, y);
            mn = fminf(mn, y);
            psum += y;
            psq = fmaf(y, y, psq);
        }
        g_ymax[(size_t)point * OO + o] = mx;
        g_ymin[(size_t)point * OO + o] = mn;
    }
    __shared__ float ss[256], s2[256];
    ss[tid] = psum; s2[tid] = psq;
    __syncthreads();
    if (tid < 64) {
        float a = ss[tid] + ss[tid + 64] + ss[tid + 128] + ss[tid + 192];
        float c = s2[tid] + s2[tid + 64] + s2[tid + 128] + s2[tid + 192];
        g_part[(size_t)blockIdx.x * 128 + tid] = a;
        g_part[(size_t)blockIdx.x * 128 + 64 + tid] = c;
    }
}

__global__ void k_reduce() {
    int i = blockIdx.x;
    int t = threadIdx.x;
    float s = 0.f;
    for (int blk = t; blk < DBLK; blk += 256) s += g_part[(size_t)blk * 128 + i];
    __shared__ float smr[256];
    smr[t] = s;
    __syncthreads();
    for (int wd = 128; wd > 0; wd >>= 1) {
        if (t < wd) smr[t] += smr[t + wd];
        __syncthreads();
    }
    if (t == 0) g_stats[i] = smr[0];
}

__global__ void k_out(const float* __restrict__ gamma, const float* __restrict__ beta,
                      float* __restrict__ out) {
    __shared__ float smT[OO][33];
    int b = blockIdx.y, n0 = blockIdx.x * 32;
    int tid = threadIdx.x;
    const float CNTf = (float)(BB * NN * KK);
#pragma unroll 1
    for (int i = tid; i < 32 * OO; i += 256) {
        int n = i >> 6, o = i & 63;
        float s = g_stats[o], s2v = g_stats[64 + o];
        float mean = s / CNTf;
        float var = s2v / CNTf - mean * mean;
        float rstd = rsqrtf(var + EPS);
        float gm = gamma[o];
        size_t yi = ((size_t)b * NN + n0 + n) * OO + o;
        float v = (gm >= 0.f) ? g_ymax[yi] : g_ymin[yi];
        float z = gm * (v - mean) * rstd + beta[o];
        z = (z >= 0.f) ? z : NEG_SLOPE * z;
        smT[o][n] = z;
    }
    __syncthreads();
#pragma unroll 1
    for (int i = tid; i < OO * 32; i += 256) {
        int o = i >> 5, n = i & 31;
        out[((size_t)b * OO + o) * NN + n0 + n] = smT[o][n];
    }
}

extern "C" void kernel_launch(void* const* d_in, const int* in_sizes, int n_in,
                              void* d_out, int out_size) {
    const float* inp = (const float*)d_in[0];
    const float* W = (const float*)d_in[1];
    const float* gamma = (const float*)d_in[2];
    const float* beta = (const float*)d_in[3];
    float* out = (float*)d_out;

    cudaFuncSetAttribute(k_prep, cudaFuncAttributeMaxDynamicSharedMemorySize, PREP_BYTES);
    cudaFuncSetAttribute(k_knn_wmma, cudaFuncAttributeMaxDynamicSharedMemorySize, DYN_BYTES);

    k_prep<<<BB * NN / 128, 128, PREP_BYTES>>>(inp, W);
    k_knn_wmma<<<dim3(NN / 128, BB), 128, DYN_BYTES>>>();
    k_gather<<<DBLK, 256>>>();
    k_reduce<<<2 * OO, 256>>>();
    k_out<<<dim3(NN / 32, BB), 256>>>(gamma, beta, out);
}